// round 1
// baseline (speedup 1.0000x reference)
#include <cuda_runtime.h>
#include <math.h>

#define NN      4096
#define NFEAT   512
#define NHID    64
#define NHEADS  8
#define NCLASS  41
#define HD      (NHEADS*NHID)   /* 512 */
#define MAXD    256
#define ALPHA   0.2f

/* scratch (static device globals: no allocation in kernel_launch) */
__device__ int   g_deg[NN];
__device__ int   g_nbr[NN*MAXD];
__device__ float g_Wh [NN*HD];          /* layout [n][h*64+d] */
__device__ float g_s1 [NHEADS*NN];
__device__ float g_s2 [NHEADS*NN];
__device__ float g_h  [NN*HD];          /* layer-1 output, [n][h*64+d] */
__device__ float g_Wh2[NN*NCLASS];
__device__ float g_p1 [NN];
__device__ float g_p2 [NN];

/* ------------------------------------------------------------------ */
/* 1. adjacency -> fixed-width neighbor lists (deterministic, ordered) */
__global__ void build_csr(const float* __restrict__ adj) {
    int row  = blockIdx.x * (blockDim.x >> 5) + (threadIdx.x >> 5);
    int lane = threadIdx.x & 31;
    if (row >= NN) return;
    const float* arow = adj + (size_t)row * NN;
    int base = 0;
    for (int j0 = 0; j0 < NN; j0 += 32) {
        float v = arow[j0 + lane];
        unsigned m = __ballot_sync(0xffffffffu, v > 0.0f);
        if (v > 0.0f) {
            int pos = base + __popc(m & ((1u << lane) - 1u));
            if (pos < MAXD) g_nbr[row * MAXD + pos] = j0 + lane;
        }
        base += __popc(m);
    }
    if (lane == 0) g_deg[row] = base < MAXD ? base : MAXD;
}

/* ------------------------------------------------------------------ */
/* 2. Wh[n][h*64+d] = sum_f x[n][f] * W_heads[h][f][d]                 */
/*    fp32 register-tiled GEMM, BM=BN=64, BK=16, 256 thr, 4x4/thread   */
__global__ void gemm1(const float* __restrict__ x, const float* __restrict__ Wv) {
    __shared__ float As[16][64];
    __shared__ float Bs[16][64];
    const int bm = blockIdx.x * 64;
    const int h  = blockIdx.y;            /* BN==64 == NHID -> one head per block col */
    const int bn = h * 64;
    const int t  = threadIdx.x;
    const int tx = t & 15, ty = t >> 4;
    const float* Bbase = Wv + (size_t)h * NFEAT * NHID;

    float acc[4][4] = {};
    const int lr = t >> 2;                /* A load: row 0..63   */
    const int lc = (t & 3) * 4;           /* A load: k sub-group */

    for (int kt = 0; kt < NFEAT; kt += 16) {
        float4 av = *(const float4*)(x + (size_t)(bm + lr) * NFEAT + kt + lc);
        As[lc + 0][lr] = av.x; As[lc + 1][lr] = av.y;
        As[lc + 2][lr] = av.z; As[lc + 3][lr] = av.w;
        /* B tile is 1024 contiguous floats: W[h][kt..kt+15][0..63] */
        *(float4*)(&Bs[0][0] + t * 4) = *(const float4*)(Bbase + kt * 64 + t * 4);
        __syncthreads();
#pragma unroll
        for (int k = 0; k < 16; k++) {
            float a[4], b[4];
#pragma unroll
            for (int i = 0; i < 4; i++) a[i] = As[k][ty * 4 + i];
#pragma unroll
            for (int j = 0; j < 4; j++) b[j] = Bs[k][tx * 4 + j];
#pragma unroll
            for (int i = 0; i < 4; i++)
#pragma unroll
                for (int j = 0; j < 4; j++) acc[i][j] += a[i] * b[j];
        }
        __syncthreads();
    }
#pragma unroll
    for (int i = 0; i < 4; i++) {
        float4 v = make_float4(acc[i][0], acc[i][1], acc[i][2], acc[i][3]);
        *(float4*)(g_Wh + (size_t)(bm + ty * 4 + i) * HD + bn + tx * 4) = v;
    }
}

/* ------------------------------------------------------------------ */
/* 3. s1[h,n] = Wh[h,n,:].a1[h]  ;  s2 likewise (a2)                   */
__global__ void s1s2(const float* __restrict__ a_heads) {
    int n    = blockIdx.x;
    int h    = threadIdx.x >> 5;          /* 8 warps = 8 heads */
    int lane = threadIdx.x & 31;
    const float* wh = g_Wh + (size_t)n * HD + h * NHID;
    const float* ah = a_heads + h * 2 * NHID;
    float v0 = wh[lane], v1 = wh[lane + 32];
    float d1 = v0 * ah[lane]        + v1 * ah[lane + 32];
    float d2 = v0 * ah[NHID + lane] + v1 * ah[NHID + lane + 32];
#pragma unroll
    for (int o = 16; o; o >>= 1) {
        d1 += __shfl_down_sync(0xffffffffu, d1, o);
        d2 += __shfl_down_sync(0xffffffffu, d2, o);
    }
    if (lane == 0) { g_s1[h * NN + n] = d1; g_s2[h * NN + n] = d2; }
}

/* ------------------------------------------------------------------ */
/* 4. layer-1 attention: masked softmax over neighbors + sparse agg    */
__global__ void attn1(void) {
    int i = blockIdx.x, h = blockIdx.y, t = threadIdx.x;   /* 64 threads */
    int deg = g_deg[i];
    __shared__ float w[MAXD];
    __shared__ int   nb[MAXD];
    __shared__ float red[64];

    float s1i  = g_s1[h * NN + i];
    float lmax = -1e30f;
    for (int k = t; k < deg; k += 64) {
        int j = g_nbr[i * MAXD + k];
        nb[k] = j;
        float e = s1i + g_s2[h * NN + j];
        e = e > 0.0f ? e : ALPHA * e;
        w[k] = e;
        lmax = fmaxf(lmax, e);
    }
    red[t] = lmax; __syncthreads();
    for (int s = 32; s; s >>= 1) { if (t < s) red[t] = fmaxf(red[t], red[t + s]); __syncthreads(); }
    float m = red[0]; __syncthreads();

    float lsum = 0.0f;
    for (int k = t; k < deg; k += 64) { float ew = __expf(w[k] - m); w[k] = ew; lsum += ew; }
    red[t] = lsum; __syncthreads();
    for (int s = 32; s; s >>= 1) { if (t < s) red[t] += red[t + s]; __syncthreads(); }
    float inv = 1.0f / red[0];

    float acc = 0.0f;
    for (int k = 0; k < deg; k++)
        acc += w[k] * g_Wh[(size_t)nb[k] * HD + h * NHID + t];
    float v = acc * inv;
    v = v > 0.0f ? v : (__expf(v) - 1.0f);                 /* elu */
    g_h[(size_t)i * HD + h * NHID + t] = v;
}

/* ------------------------------------------------------------------ */
/* 5. Wh2 = h @ W_out (512x41), fused p1/p2 = Wh2 . a_out halves       */
__global__ void out_proj(const float* __restrict__ W_out, const float* __restrict__ a_out) {
    int i = blockIdx.x, t = threadIdx.x;                   /* 64 threads */
    __shared__ float hs[HD];
    __shared__ float ws[NCLASS];
    for (int k = t; k < HD; k += 64) hs[k] = g_h[(size_t)i * HD + k];
    __syncthreads();
    if (t < NCLASS) {
        float acc = 0.0f;
#pragma unroll 8
        for (int k = 0; k < HD; k++) acc += hs[k] * W_out[k * NCLASS + t];
        g_Wh2[i * NCLASS + t] = acc;
        ws[t] = acc;
    }
    __syncthreads();
    if (t == 0) {
        float p1 = 0.0f, p2 = 0.0f;
        for (int c = 0; c < NCLASS; c++) {
            p1 += ws[c] * a_out[c];
            p2 += ws[c] * a_out[NCLASS + c];
        }
        g_p1[i] = p1; g_p2[i] = p2;
    }
}

/* ------------------------------------------------------------------ */
/* 6. layer-2 attention + elu + log_softmax over 41 classes            */
__global__ void attn2(float* __restrict__ out) {
    int i = blockIdx.x, t = threadIdx.x;                   /* 64 threads */
    int deg = g_deg[i];
    __shared__ float w[MAXD];
    __shared__ int   nb[MAXD];
    __shared__ float red[64];

    float p1i  = g_p1[i];
    float lmax = -1e30f;
    for (int k = t; k < deg; k += 64) {
        int j = g_nbr[i * MAXD + k];
        nb[k] = j;
        float e = p1i + g_p2[j];
        e = e > 0.0f ? e : ALPHA * e;
        w[k] = e;
        lmax = fmaxf(lmax, e);
    }
    red[t] = lmax; __syncthreads();
    for (int s = 32; s; s >>= 1) { if (t < s) red[t] = fmaxf(red[t], red[t + s]); __syncthreads(); }
    float m = red[0]; __syncthreads();

    float lsum = 0.0f;
    for (int k = t; k < deg; k += 64) { float ew = __expf(w[k] - m); w[k] = ew; lsum += ew; }
    red[t] = lsum; __syncthreads();
    for (int s = 32; s; s >>= 1) { if (t < s) red[t] += red[t + s]; __syncthreads(); }
    float inv = 1.0f / red[0];
    __syncthreads();

    float o = -1e30f;
    if (t < NCLASS) {
        float acc = 0.0f;
        for (int k = 0; k < deg; k++)
            acc += w[k] * g_Wh2[nb[k] * NCLASS + t];
        o = acc * inv;
        o = o > 0.0f ? o : (__expf(o) - 1.0f);             /* elu */
    }
    /* log_softmax over the 41 classes */
    red[t] = o; __syncthreads();
    for (int s = 32; s; s >>= 1) { if (t < s) red[t] = fmaxf(red[t], red[t + s]); __syncthreads(); }
    float mx = red[0]; __syncthreads();
    float ex = (t < NCLASS) ? __expf(o - mx) : 0.0f;
    red[t] = ex; __syncthreads();
    for (int s = 32; s; s >>= 1) { if (t < s) red[t] += red[t + s]; __syncthreads(); }
    float lse = mx + __logf(red[0]);
    if (t < NCLASS) out[i * NCLASS + t] = o - lse;
}

/* ------------------------------------------------------------------ */
extern "C" void kernel_launch(void* const* d_in, const int* in_sizes, int n_in,
                              void* d_out, int out_size) {
    /* map inputs by element count (all distinct) to be ordering-proof */
    const float *x = 0, *adj = 0, *W_heads = 0, *a_heads = 0, *W_out = 0, *a_out = 0;
    for (int i = 0; i < n_in; i++) {
        switch (in_sizes[i]) {
            case NN*NFEAT:            x       = (const float*)d_in[i]; break; /* 2097152 */
            case NN*NN:               adj     = (const float*)d_in[i]; break; /* 16777216 */
            case NHEADS*NFEAT*NHID:   W_heads = (const float*)d_in[i]; break; /* 262144 */
            case NHEADS*2*NHID:       a_heads = (const float*)d_in[i]; break; /* 1024 */
            case HD*NCLASS:           W_out   = (const float*)d_in[i]; break; /* 20992 */
            case 2*NCLASS:            a_out   = (const float*)d_in[i]; break; /* 82 */
        }
    }
    float* out = (float*)d_out;

    build_csr<<<NN / 4, 128>>>(adj);
    gemm1   <<<dim3(NN / 64, NHEADS), 256>>>(x, W_heads);
    s1s2    <<<NN, 256>>>(a_heads);
    attn1   <<<dim3(NN, NHEADS), 64>>>();
    out_proj<<<NN, 64>>>(W_out, a_out);
    attn2   <<<NN, 64>>>(out);
}

// round 2
// speedup vs baseline: 1.6082x; 1.6082x over previous
#include <cuda_runtime.h>
#include <math.h>

#define NN      4096
#define NFEAT   512
#define NHID    64
#define NHEADS  8
#define NCLASS  41
#define HD      (NHEADS*NHID)   /* 512 */
#define MAXD    256
#define ALPHA   0.2f

/* scratch (static device globals: no allocation in kernel_launch) */
__device__ int   g_deg[NN];
__device__ int   g_nbr[NN*MAXD];
__device__ float g_Wh [NN*HD];          /* layout [n][h*64+d] */
__device__ float g_s1 [NHEADS*NN];
__device__ float g_s2 [NHEADS*NN];
__device__ float g_h  [NN*HD];          /* layer-1 output, [n][h*64+d] */
__device__ float g_Wh2[NN*NCLASS];
__device__ float g_p1 [NN];
__device__ float g_p2 [NN];

/* ------------------------------------------------------------------ */
/* Fused: blocks 0..511 do gemm1 (FMA-bound), 512..1023 do CSR build   */
/* (DRAM-bound). Disjoint pipes -> they overlap on the SMs.            */
__global__ void csr_gemm1(const float* __restrict__ adj,
                          const float* __restrict__ x,
                          const float* __restrict__ Wv) {
    __shared__ float As[16][64];
    __shared__ float Bs[16][64];
    const int bid = blockIdx.x;
    const int t   = threadIdx.x;

    if (bid < 512) {
        /* ---- gemm1: Wh[n][h*64+d] = sum_f x[n][f]*W[h][f][d] ---- */
        const int bm = (bid & 63) * 64;
        const int h  = bid >> 6;
        const int bn = h * 64;
        const int tx = t & 15, ty = t >> 4;
        const float* Bbase = Wv + (size_t)h * NFEAT * NHID;

        float acc[4][4] = {};
        const int lr = t >> 2;
        const int lc = (t & 3) * 4;

        for (int kt = 0; kt < NFEAT; kt += 16) {
            float4 av = *(const float4*)(x + (size_t)(bm + lr) * NFEAT + kt + lc);
            As[lc + 0][lr] = av.x; As[lc + 1][lr] = av.y;
            As[lc + 2][lr] = av.z; As[lc + 3][lr] = av.w;
            *(float4*)(&Bs[0][0] + t * 4) = *(const float4*)(Bbase + kt * 64 + t * 4);
            __syncthreads();
#pragma unroll
            for (int k = 0; k < 16; k++) {
                float a[4], b[4];
#pragma unroll
                for (int i = 0; i < 4; i++) a[i] = As[k][ty * 4 + i];
#pragma unroll
                for (int j = 0; j < 4; j++) b[j] = Bs[k][tx * 4 + j];
#pragma unroll
                for (int i = 0; i < 4; i++)
#pragma unroll
                    for (int j = 0; j < 4; j++) acc[i][j] += a[i] * b[j];
            }
            __syncthreads();
        }
#pragma unroll
        for (int i = 0; i < 4; i++) {
            float4 v = make_float4(acc[i][0], acc[i][1], acc[i][2], acc[i][3]);
            *(float4*)(g_Wh + (size_t)(bm + ty * 4 + i) * HD + bn + tx * 4) = v;
        }
    } else {
        /* ---- build_csr: warp per row, float4 + 4 ballots ---- */
        const int warp = t >> 5, lane = t & 31;
        const int row  = (bid - 512) * 8 + warp;
        const float4* arow = (const float4*)(adj + (size_t)row * NN);
        const unsigned lt = (1u << lane) - 1u;
        int base = 0;
        for (int j0 = 0; j0 < NN / 4; j0 += 32) {
            float4 v = arow[j0 + lane];
            unsigned m0 = __ballot_sync(0xffffffffu, v.x > 0.0f);
            unsigned m1 = __ballot_sync(0xffffffffu, v.y > 0.0f);
            unsigned m2 = __ballot_sync(0xffffffffu, v.z > 0.0f);
            unsigned m3 = __ballot_sync(0xffffffffu, v.w > 0.0f);
            int below = __popc(m0 & lt) + __popc(m1 & lt) +
                        __popc(m2 & lt) + __popc(m3 & lt);
            int jb = (j0 + lane) * 4;
            int p  = base + below;
            if (v.x > 0.0f) { if (p < MAXD) g_nbr[row * MAXD + p] = jb + 0; p++; }
            if (v.y > 0.0f) { if (p < MAXD) g_nbr[row * MAXD + p] = jb + 1; p++; }
            if (v.z > 0.0f) { if (p < MAXD) g_nbr[row * MAXD + p] = jb + 2; p++; }
            if (v.w > 0.0f) { if (p < MAXD) g_nbr[row * MAXD + p] = jb + 3; p++; }
            base += __popc(m0) + __popc(m1) + __popc(m2) + __popc(m3);
        }
        if (lane == 0) g_deg[row] = base < MAXD ? base : MAXD;
    }
}

/* ------------------------------------------------------------------ */
/* s1[h,n] = Wh[n,h,:].a1[h]  ;  s2 likewise (a2)                      */
__global__ void s1s2(const float* __restrict__ a_heads) {
    int n    = blockIdx.x;
    int h    = threadIdx.x >> 5;          /* 8 warps = 8 heads */
    int lane = threadIdx.x & 31;
    const float* wh = g_Wh + (size_t)n * HD + h * NHID;
    const float* ah = a_heads + h * 2 * NHID;
    float v0 = wh[lane], v1 = wh[lane + 32];
    float d1 = v0 * ah[lane]        + v1 * ah[lane + 32];
    float d2 = v0 * ah[NHID + lane] + v1 * ah[NHID + lane + 32];
#pragma unroll
    for (int o = 16; o; o >>= 1) {
        d1 += __shfl_down_sync(0xffffffffu, d1, o);
        d2 += __shfl_down_sync(0xffffffffu, d2, o);
    }
    if (lane == 0) { g_s1[h * NN + n] = d1; g_s2[h * NN + n] = d2; }
}

/* ------------------------------------------------------------------ */
/* layer-1 attention: block per node, warp per head, shuffle softmax   */
__global__ void attn1(void) {
    const int i = blockIdx.x, t = threadIdx.x;
    const int h = t >> 5, lane = t & 31;
    __shared__ int   nb[MAXD];
    __shared__ float ew[NHEADS][MAXD];

    const int deg = g_deg[i];
    if (t < deg) nb[t] = g_nbr[i * MAXD + t];
    __syncthreads();

    const float s1i = g_s1[h * NN + i];
    float ev[8];
    float m = -1e30f;
#pragma unroll
    for (int c = 0; c < 8; c++) {
        int k = c * 32 + lane;
        float e = -1e30f;
        if (k < deg) {
            e = s1i + g_s2[h * NN + nb[k]];
            e = e > 0.0f ? e : ALPHA * e;
        }
        ev[c] = e; m = fmaxf(m, e);
    }
#pragma unroll
    for (int o = 16; o; o >>= 1) m = fmaxf(m, __shfl_xor_sync(0xffffffffu, m, o));
    float s = 0.0f;
#pragma unroll
    for (int c = 0; c < 8; c++) {
        int k = c * 32 + lane;
        if (k < deg) { float x = __expf(ev[c] - m); ew[h][k] = x; s += x; }
    }
#pragma unroll
    for (int o = 16; o; o >>= 1) s += __shfl_xor_sync(0xffffffffu, s, o);
    const float inv = 1.0f / s;
    __syncwarp();

    /* aggregation: warp h computes 64 outputs (lane, lane+32), 4-way unroll */
    const int hoff = h * NHID;
    float a0 = 0, a1 = 0, b0 = 0, b1 = 0, c0 = 0, c1 = 0, d0 = 0, d1 = 0;
    int k = 0;
    for (; k + 4 <= deg; k += 4) {
        float w0 = ew[h][k], w1 = ew[h][k + 1], w2 = ew[h][k + 2], w3 = ew[h][k + 3];
        const float* r0 = g_Wh + (size_t)nb[k]     * HD + hoff;
        const float* r1 = g_Wh + (size_t)nb[k + 1] * HD + hoff;
        const float* r2 = g_Wh + (size_t)nb[k + 2] * HD + hoff;
        const float* r3 = g_Wh + (size_t)nb[k + 3] * HD + hoff;
        a0 += w0 * r0[lane]; a1 += w0 * r0[lane + 32];
        b0 += w1 * r1[lane]; b1 += w1 * r1[lane + 32];
        c0 += w2 * r2[lane]; c1 += w2 * r2[lane + 32];
        d0 += w3 * r3[lane]; d1 += w3 * r3[lane + 32];
    }
    for (; k < deg; k++) {
        float w0 = ew[h][k];
        const float* r0 = g_Wh + (size_t)nb[k] * HD + hoff;
        a0 += w0 * r0[lane]; a1 += w0 * r0[lane + 32];
    }
    float v0 = (a0 + b0 + c0 + d0) * inv;
    float v1 = (a1 + b1 + c1 + d1) * inv;
    v0 = v0 > 0.0f ? v0 : (__expf(v0) - 1.0f);
    v1 = v1 > 0.0f ? v1 : (__expf(v1) - 1.0f);
    g_h[(size_t)i * HD + hoff + lane]      = v0;
    g_h[(size_t)i * HD + hoff + lane + 32] = v1;
}

/* ------------------------------------------------------------------ */
/* Wh2 = h @ W_out, 4-way K-split; fused p1/p2 = Wh2 . a_out halves    */
__global__ void out_proj(const float* __restrict__ W_out, const float* __restrict__ a_out) {
    const int i = blockIdx.x, t = threadIdx.x;      /* 256 threads */
    __shared__ float hs[HD];
    __shared__ float part[4][NCLASS];
    __shared__ float ws[NCLASS];
    for (int k = t; k < HD; k += 256) hs[k] = g_h[(size_t)i * HD + k];
    __syncthreads();
    if (t < 4 * NCLASS) {
        const int seg = t / NCLASS, c = t - seg * NCLASS;
        const float* w = W_out + c;
        float acc = 0.0f;
        const int k0 = seg * 128;
#pragma unroll 8
        for (int k = k0; k < k0 + 128; k++) acc += hs[k] * w[(size_t)k * NCLASS];
        part[seg][c] = acc;
    }
    __syncthreads();
    if (t < NCLASS) {
        float v = part[0][t] + part[1][t] + part[2][t] + part[3][t];
        g_Wh2[i * NCLASS + t] = v;
        ws[t] = v;
    }
    __syncthreads();
    if (t < 32) {
        float p1 = ws[t] * a_out[t];
        float p2 = ws[t] * a_out[NCLASS + t];
        if (t + 32 < NCLASS) {
            p1 += ws[t + 32] * a_out[t + 32];
            p2 += ws[t + 32] * a_out[NCLASS + t + 32];
        }
#pragma unroll
        for (int o = 16; o; o >>= 1) {
            p1 += __shfl_down_sync(0xffffffffu, p1, o);
            p2 += __shfl_down_sync(0xffffffffu, p2, o);
        }
        if (t == 0) { g_p1[i] = p1; g_p2[i] = p2; }
    }
}

/* ------------------------------------------------------------------ */
/* layer-2 attention + elu + log_softmax over 41 classes               */
__global__ void attn2(float* __restrict__ out) {
    int i = blockIdx.x, t = threadIdx.x;                   /* 64 threads */
    int deg = g_deg[i];
    __shared__ float w[MAXD];
    __shared__ int   nb[MAXD];
    __shared__ float red[64];

    float p1i  = g_p1[i];
    float lmax = -1e30f;
    for (int k = t; k < deg; k += 64) {
        int j = g_nbr[i * MAXD + k];
        nb[k] = j;
        float e = p1i + g_p2[j];
        e = e > 0.0f ? e : ALPHA * e;
        w[k] = e;
        lmax = fmaxf(lmax, e);
    }
    red[t] = lmax; __syncthreads();
    for (int s = 32; s; s >>= 1) { if (t < s) red[t] = fmaxf(red[t], red[t + s]); __syncthreads(); }
    float m = red[0]; __syncthreads();

    float lsum = 0.0f;
    for (int k = t; k < deg; k += 64) { float ewv = __expf(w[k] - m); w[k] = ewv; lsum += ewv; }
    red[t] = lsum; __syncthreads();
    for (int s = 32; s; s >>= 1) { if (t < s) red[t] += red[t + s]; __syncthreads(); }
    float inv = 1.0f / red[0];
    __syncthreads();

    float o = -1e30f;
    if (t < NCLASS) {
        float acc0 = 0.0f, acc1 = 0.0f;
        int k = 0;
        for (; k + 2 <= deg; k += 2) {
            acc0 += w[k]     * g_Wh2[nb[k]     * NCLASS + t];
            acc1 += w[k + 1] * g_Wh2[nb[k + 1] * NCLASS + t];
        }
        if (k < deg) acc0 += w[k] * g_Wh2[nb[k] * NCLASS + t];
        o = (acc0 + acc1) * inv;
        o = o > 0.0f ? o : (__expf(o) - 1.0f);             /* elu */
    }
    /* log_softmax over the 41 classes */
    red[t] = o; __syncthreads();
    for (int s = 32; s; s >>= 1) { if (t < s) red[t] = fmaxf(red[t], red[t + s]); __syncthreads(); }
    float mx = red[0]; __syncthreads();
    float ex = (t < NCLASS) ? __expf(o - mx) : 0.0f;
    red[t] = ex; __syncthreads();
    for (int s = 32; s; s >>= 1) { if (t < s) red[t] += red[t + s]; __syncthreads(); }
    float lse = mx + __logf(red[0]);
    if (t < NCLASS) out[i * NCLASS + t] = o - lse;
}

/* ------------------------------------------------------------------ */
extern "C" void kernel_launch(void* const* d_in, const int* in_sizes, int n_in,
                              void* d_out, int out_size) {
    const float *x = 0, *adj = 0, *W_heads = 0, *a_heads = 0, *W_out = 0, *a_out = 0;
    for (int i = 0; i < n_in; i++) {
        switch (in_sizes[i]) {
            case NN*NFEAT:            x       = (const float*)d_in[i]; break;
            case NN*NN:               adj     = (const float*)d_in[i]; break;
            case NHEADS*NFEAT*NHID:   W_heads = (const float*)d_in[i]; break;
            case NHEADS*2*NHID:       a_heads = (const float*)d_in[i]; break;
            case HD*NCLASS:           W_out   = (const float*)d_in[i]; break;
            case 2*NCLASS:            a_out   = (const float*)d_in[i]; break;
        }
    }
    float* out = (float*)d_out;

    csr_gemm1<<<1024, 256>>>(adj, x, W_heads);
    s1s2    <<<NN, 256>>>(a_heads);
    attn1   <<<NN, 256>>>();
    out_proj<<<NN, 256>>>(W_out, a_out);
    attn2   <<<NN, 64>>>(out);
}

// round 4
// speedup vs baseline: 1.8303x; 1.1382x over previous
#include <cuda_runtime.h>
#include <cuda_bf16.h>
#include <mma.h>
#include <math.h>
#include <stdint.h>

#define NN      4096
#define NFEAT   512
#define NHID    64
#define NHEADS  8
#define NCLASS  41
#define HD      (NHEADS*NHID)   /* 512 */
#define MAXD    256
#define ALPHA   0.2f

using namespace nvcuda;

/* scratch */
__device__ int   g_deg[NN];
__device__ int   g_nbr[NN*MAXD];
__device__ float g_Wh [NN*HD];          /* [n][h*64+d] */
__device__ float g_s1 [NHEADS*NN];
__device__ float g_s2 [NHEADS*NN];
__device__ float g_h  [NN*HD];
__device__ float g_Wh2[NN*NCLASS];
__device__ float g_p1 [NN];
__device__ float g_p2 [NN];

/* ------------------------------------------------------------------ */
/* fused1: blocks 0..511 -> bf16-split wmma GEMM (Wh = x @ W_head)     */
/*         + fused s1/s2 epilogue. blocks 512..1023 -> CSR build.      */
/* A tiles: 64x16, ldm 24 (48B rows). B tiles: 16x64, ldm 72 (144B).   */
__global__ void __launch_bounds__(256, 4)
fused1(const float* __restrict__ adj, const float* __restrict__ x,
       const float* __restrict__ Wv,  const float* __restrict__ a_heads) {
    const int bid = blockIdx.x, t = threadIdx.x;
    const int wid = t >> 5, lane = t & 31;

    if (bid >= 512) {
        /* ---- CSR build: warp per row (8 warps -> 8 rows/block) ---- */
        const int row = (bid - 512) * 8 + wid;
        const float4* arow = (const float4*)(adj + (size_t)row * NN);
        const unsigned lt = (1u << lane) - 1u;
        int base = 0;
        for (int j0 = 0; j0 < NN / 4; j0 += 32) {
            float4 v = arow[j0 + lane];
            unsigned m0 = __ballot_sync(0xffffffffu, v.x > 0.0f);
            unsigned m1 = __ballot_sync(0xffffffffu, v.y > 0.0f);
            unsigned m2 = __ballot_sync(0xffffffffu, v.z > 0.0f);
            unsigned m3 = __ballot_sync(0xffffffffu, v.w > 0.0f);
            int below = __popc(m0 & lt) + __popc(m1 & lt) + __popc(m2 & lt) + __popc(m3 & lt);
            int jb = (j0 + lane) * 4;
            int p  = base + below;
            if (v.x > 0.0f) { if (p < MAXD) g_nbr[row * MAXD + p] = jb + 0; p++; }
            if (v.y > 0.0f) { if (p < MAXD) g_nbr[row * MAXD + p] = jb + 1; p++; }
            if (v.z > 0.0f) { if (p < MAXD) g_nbr[row * MAXD + p] = jb + 2; p++; }
            if (v.w > 0.0f) { if (p < MAXD) g_nbr[row * MAXD + p] = jb + 3; p++; }
            base += __popc(m0) + __popc(m1) + __popc(m2) + __popc(m3);
        }
        if (lane == 0) g_deg[row] = base < MAXD ? base : MAXD;
        return;
    }

    /* ---- GEMM: block = 64 rows of x, one head; 8 warps 4x2 ---- */
    __shared__ __nv_bfloat16 As_hi[64 * 24];
    __shared__ __nv_bfloat16 As_lo[64 * 24];
    __shared__ __nv_bfloat16 Bs_hi[16 * 72];
    __shared__ __nv_bfloat16 Bs_lo[16 * 72];
    __shared__ float         Cs[64 * 72];
    __shared__ float         s_a12[128];

    const int bm = (bid & 63) * 64;
    const int h  = bid >> 6;
    const int wm = wid & 3;              /* m-slice 0..3 (16 rows)   */
    const int wn = wid >> 2;             /* n-slice 0..1 (32 cols)   */
    const float* Wb = Wv + (size_t)h * NFEAT * NHID;

    if (t < 128) s_a12[t] = a_heads[h * 128 + t];

    wmma::fragment<wmma::matrix_a, 16, 16, 16, __nv_bfloat16, wmma::row_major> ah, al;
    wmma::fragment<wmma::matrix_b, 16, 16, 16, __nv_bfloat16, wmma::row_major> bh, bl;
    wmma::fragment<wmma::accumulator, 16, 16, 16, float> acc[2];
    wmma::fill_fragment(acc[0], 0.0f);
    wmma::fill_fragment(acc[1], 0.0f);

    /* A-load coords: each of 256 threads handles one float4 of 64x16 */
    const int ar = t >> 2, ac = (t & 3) * 4;
    /* B-load coords: one float4 of 16x64 */
    const int bk = t >> 4, bn = (t & 15) * 4;

    for (int kt = 0; kt < NFEAT; kt += 16) {
        float4 av = *(const float4*)(x + (size_t)(bm + ar) * NFEAT + kt + ac);
        float4 bv = *(const float4*)(Wb + (size_t)(kt + bk) * NHID + bn);
        {
            __nv_bfloat162 h0, h1, l0, l1;
            h0.x = __float2bfloat16(av.x); h0.y = __float2bfloat16(av.y);
            h1.x = __float2bfloat16(av.z); h1.y = __float2bfloat16(av.w);
            l0.x = __float2bfloat16(av.x - __bfloat162float(h0.x));
            l0.y = __float2bfloat16(av.y - __bfloat162float(h0.y));
            l1.x = __float2bfloat16(av.z - __bfloat162float(h1.x));
            l1.y = __float2bfloat16(av.w - __bfloat162float(h1.y));
            *(__nv_bfloat162*)(As_hi + ar * 24 + ac)     = h0;
            *(__nv_bfloat162*)(As_hi + ar * 24 + ac + 2) = h1;
            *(__nv_bfloat162*)(As_lo + ar * 24 + ac)     = l0;
            *(__nv_bfloat162*)(As_lo + ar * 24 + ac + 2) = l1;
        }
        {
            __nv_bfloat162 h0, h1, l0, l1;
            h0.x = __float2bfloat16(bv.x); h0.y = __float2bfloat16(bv.y);
            h1.x = __float2bfloat16(bv.z); h1.y = __float2bfloat16(bv.w);
            l0.x = __float2bfloat16(bv.x - __bfloat162float(h0.x));
            l0.y = __float2bfloat16(bv.y - __bfloat162float(h0.y));
            l1.x = __float2bfloat16(bv.z - __bfloat162float(h1.x));
            l1.y = __float2bfloat16(bv.w - __bfloat162float(h1.y));
            *(__nv_bfloat162*)(Bs_hi + bk * 72 + bn)     = h0;
            *(__nv_bfloat162*)(Bs_hi + bk * 72 + bn + 2) = h1;
            *(__nv_bfloat162*)(Bs_lo + bk * 72 + bn)     = l0;
            *(__nv_bfloat162*)(Bs_lo + bk * 72 + bn + 2) = l1;
        }
        __syncthreads();

        wmma::load_matrix_sync(ah, As_hi + wm * 16 * 24, 24);
        wmma::load_matrix_sync(al, As_lo + wm * 16 * 24, 24);
#pragma unroll
        for (int f = 0; f < 2; f++) {
            wmma::load_matrix_sync(bh, Bs_hi + wn * 32 + f * 16, 72);
            wmma::load_matrix_sync(bl, Bs_lo + wn * 32 + f * 16, 72);
            wmma::mma_sync(acc[f], ah, bh, acc[f]);
            wmma::mma_sync(acc[f], ah, bl, acc[f]);
            wmma::mma_sync(acc[f], al, bh, acc[f]);
        }
        __syncthreads();
    }

    /* epilogue: stage C in smem, fused s1/s2, coalesced Wh store */
#pragma unroll
    for (int f = 0; f < 2; f++)
        wmma::store_matrix_sync(Cs + wm * 16 * 72 + wn * 32 + f * 16, acc[f],
                                72, wmma::mem_row_major);
    __syncthreads();

    if (t < 64) {
        float s1 = 0.0f, s2 = 0.0f;
        const float* row = Cs + t * 72;
#pragma unroll 16
        for (int c = 0; c < 64; c++) {
            float f = row[c];
            s1 += f * s_a12[c];
            s2 += f * s_a12[64 + c];
        }
        g_s1[h * NN + bm + t] = s1;
        g_s2[h * NN + bm + t] = s2;
    }
    for (int idx = t; idx < 64 * 64; idx += 256) {
        int rr = idx >> 6, cc = idx & 63;
        g_Wh[(size_t)(bm + rr) * HD + h * NHID + cc] = Cs[rr * 72 + cc];
    }
}

/* ------------------------------------------------------------------ */
/* layer-1 attention: block per node, warp per head, shuffle softmax   */
__global__ void attn1(void) {
    const int i = blockIdx.x, t = threadIdx.x;
    const int h = t >> 5, lane = t & 31;
    __shared__ int   nb[MAXD];
    __shared__ float ew[NHEADS][MAXD];

    const int deg = g_deg[i];
    if (t < deg) nb[t] = g_nbr[i * MAXD + t];
    __syncthreads();

    const float s1i = g_s1[h * NN + i];
    float ev[8];
    float m = -1e30f;
#pragma unroll
    for (int c = 0; c < 8; c++) {
        int k = c * 32 + lane;
        float e = -1e30f;
        if (k < deg) {
            e = s1i + g_s2[h * NN + nb[k]];
            e = e > 0.0f ? e : ALPHA * e;
        }
        ev[c] = e; m = fmaxf(m, e);
    }
#pragma unroll
    for (int o = 16; o; o >>= 1) m = fmaxf(m, __shfl_xor_sync(0xffffffffu, m, o));
    float s = 0.0f;
#pragma unroll
    for (int c = 0; c < 8; c++) {
        int k = c * 32 + lane;
        if (k < deg) { float x = __expf(ev[c] - m); ew[h][k] = x; s += x; }
    }
#pragma unroll
    for (int o = 16; o; o >>= 1) s += __shfl_xor_sync(0xffffffffu, s, o);
    const float inv = 1.0f / s;
    __syncwarp();

    const int hoff = h * NHID;
    float a0 = 0, a1 = 0, b0 = 0, b1 = 0, c0 = 0, c1 = 0, d0 = 0, d1 = 0;
    int k = 0;
    for (; k + 4 <= deg; k += 4) {
        float w0 = ew[h][k], w1 = ew[h][k + 1], w2 = ew[h][k + 2], w3 = ew[h][k + 3];
        const float* r0 = g_Wh + (size_t)nb[k]     * HD + hoff;
        const float* r1 = g_Wh + (size_t)nb[k + 1] * HD + hoff;
        const float* r2 = g_Wh + (size_t)nb[k + 2] * HD + hoff;
        const float* r3 = g_Wh + (size_t)nb[k + 3] * HD + hoff;
        a0 += w0 * r0[lane]; a1 += w0 * r0[lane + 32];
        b0 += w1 * r1[lane]; b1 += w1 * r1[lane + 32];
        c0 += w2 * r2[lane]; c1 += w2 * r2[lane + 32];
        d0 += w3 * r3[lane]; d1 += w3 * r3[lane + 32];
    }
    for (; k < deg; k++) {
        float w0 = ew[h][k];
        const float* r0 = g_Wh + (size_t)nb[k] * HD + hoff;
        a0 += w0 * r0[lane]; a1 += w0 * r0[lane + 32];
    }
    float v0 = (a0 + b0 + c0 + d0) * inv;
    float v1 = (a1 + b1 + c1 + d1) * inv;
    v0 = v0 > 0.0f ? v0 : (__expf(v0) - 1.0f);
    v1 = v1 > 0.0f ? v1 : (__expf(v1) - 1.0f);
    g_h[(size_t)i * HD + hoff + lane]      = v0;
    g_h[(size_t)i * HD + hoff + lane + 32] = v1;
}

/* ------------------------------------------------------------------ */
/* out_proj: tiled GEMM Wh2 = h @ W_out (512x41), fused p1/p2          */
__global__ void out_proj(const float* __restrict__ W_out, const float* __restrict__ a_out) {
    __shared__ float As[32][33];
    __shared__ float Bs[32][48];
    __shared__ float Cs2[32][48];
    const int b = blockIdx.x, t = threadIdx.x;
    const int bm = b * 32;
    const int tx = t & 15, ty = t >> 4;
    float acc[2][3] = {};

    for (int kt = 0; kt < HD; kt += 32) {
        {
            int r = t >> 3, c4 = (t & 7) * 4;
            float4 v = *(const float4*)(g_h + (size_t)(bm + r) * HD + kt + c4);
            As[c4][r] = v.x; As[c4 + 1][r] = v.y; As[c4 + 2][r] = v.z; As[c4 + 3][r] = v.w;
        }
        for (int i = t; i < 32 * 48; i += 256) {
            int kk = i / 48, c = i - kk * 48;
            Bs[kk][c] = (c < NCLASS) ? W_out[(size_t)(kt + kk) * NCLASS + c] : 0.0f;
        }
        __syncthreads();
#pragma unroll 8
        for (int k = 0; k < 32; k++) {
            float a0 = As[k][ty * 2], a1 = As[k][ty * 2 + 1];
            float b0 = Bs[k][tx * 3], b1 = Bs[k][tx * 3 + 1], b2 = Bs[k][tx * 3 + 2];
            acc[0][0] += a0 * b0; acc[0][1] += a0 * b1; acc[0][2] += a0 * b2;
            acc[1][0] += a1 * b0; acc[1][1] += a1 * b1; acc[1][2] += a1 * b2;
        }
        __syncthreads();
    }
#pragma unroll
    for (int i = 0; i < 2; i++)
#pragma unroll
        for (int j = 0; j < 3; j++) {
            int r = ty * 2 + i, c = tx * 3 + j;
            Cs2[r][c] = acc[i][j];
            if (c < NCLASS) g_Wh2[(size_t)(bm + r) * NCLASS + c] = acc[i][j];
        }
    __syncthreads();
    if (t < 32) {
        float p1 = 0.0f, p2 = 0.0f;
        for (int c = 0; c < NCLASS; c++) {
            p1 += Cs2[t][c] * a_out[c];
            p2 += Cs2[t][c] * a_out[NCLASS + c];
        }
        g_p1[bm + t] = p1; g_p2[bm + t] = p2;
    }
}

/* ------------------------------------------------------------------ */
/* layer-2 attention + elu + log_softmax                               */
__global__ void attn2(float* __restrict__ out) {
    int i = blockIdx.x, t = threadIdx.x;                   /* 64 threads */
    int deg = g_deg[i];
    __shared__ float w[MAXD];
    __shared__ int   nb[MAXD];
    __shared__ float red[64];

    float p1i  = g_p1[i];
    float lmax = -1e30f;
    for (int k = t; k < deg; k += 64) {
        int j = g_nbr[i * MAXD + k];
        nb[k] = j;
        float e = p1i + g_p2[j];
        e = e > 0.0f ? e : ALPHA * e;
        w[k] = e;
        lmax = fmaxf(lmax, e);
    }
    red[t] = lmax; __syncthreads();
    for (int s = 32; s; s >>= 1) { if (t < s) red[t] = fmaxf(red[t], red[t + s]); __syncthreads(); }
    float m = red[0]; __syncthreads();

    float lsum = 0.0f;
    for (int k = t; k < deg; k += 64) { float ewv = __expf(w[k] - m); w[k] = ewv; lsum += ewv; }
    red[t] = lsum; __syncthreads();
    for (int s = 32; s; s >>= 1) { if (t < s) red[t] += red[t + s]; __syncthreads(); }
    float inv = 1.0f / red[0];
    __syncthreads();

    float o = -1e30f;
    if (t < NCLASS) {
        float acc0 = 0.0f, acc1 = 0.0f;
        int k = 0;
        for (; k + 2 <= deg; k += 2) {
            acc0 += w[k]     * g_Wh2[nb[k]     * NCLASS + t];
            acc1 += w[k + 1] * g_Wh2[nb[k + 1] * NCLASS + t];
        }
        if (k < deg) acc0 += w[k] * g_Wh2[nb[k] * NCLASS + t];
        o = (acc0 + acc1) * inv;
        o = o > 0.0f ? o : (__expf(o) - 1.0f);
    }
    red[t] = o; __syncthreads();
    for (int s = 32; s; s >>= 1) { if (t < s) red[t] = fmaxf(red[t], red[t + s]); __syncthreads(); }
    float mx = red[0]; __syncthreads();
    float ex = (t < NCLASS) ? __expf(o - mx) : 0.0f;
    red[t] = ex; __syncthreads();
    for (int s = 32; s; s >>= 1) { if (t < s) red[t] += red[t + s]; __syncthreads(); }
    float lse = mx + __logf(red[0]);
    if (t < NCLASS) out[i * NCLASS + t] = o - lse;
}

/* ------------------------------------------------------------------ */
extern "C" void kernel_launch(void* const* d_in, const int* in_sizes, int n_in,
                              void* d_out, int out_size) {
    const float *x = 0, *adj = 0, *W_heads = 0, *a_heads = 0, *W_out = 0, *a_out = 0;
    for (int i = 0; i < n_in; i++) {
        switch (in_sizes[i]) {
            case NN*NFEAT:            x       = (const float*)d_in[i]; break;
            case NN*NN:               adj     = (const float*)d_in[i]; break;
            case NHEADS*NFEAT*NHID:   W_heads = (const float*)d_in[i]; break;
            case NHEADS*2*NHID:       a_heads = (const float*)d_in[i]; break;
            case HD*NCLASS:           W_out   = (const float*)d_in[i]; break;
            case 2*NCLASS:            a_out   = (const float*)d_in[i]; break;
        }
    }
    float* out = (float*)d_out;

    fused1  <<<1024, 256>>>(adj, x, W_heads, a_heads);
    attn1   <<<NN, 256>>>();
    out_proj<<<NN / 32, 256>>>(W_out, a_out);
    attn2   <<<NN, 64>>>(out);
}